// round 1
// baseline (speedup 1.0000x reference)
#include <cuda_runtime.h>
#include <cstdint>
#include <cstddef>

// Problem dims (fixed by the dataset)
#define NU   8192
#define NIT  8192
#define DIN  2048
#define DH   2048
#define NTOT (NU + NIT)

// 128 MiB scratch for the intermediate `support` matrix (alloc-free rule:
// __device__ global array).
__device__ float g_support[(size_t)NTOT * DH];

static __device__ __forceinline__ uint32_t f2tf32(float x) {
    uint32_t r;
    asm("cvt.rna.tf32.f32 %0, %1;" : "=r"(r) : "f"(x));
    return r;
}

static __device__ __forceinline__ void mma_tf32(float c[4], const uint32_t a[4],
                                                const uint32_t b[2]) {
    asm volatile(
        "mma.sync.aligned.m16n8k8.row.col.f32.tf32.tf32.f32 "
        "{%0,%1,%2,%3}, {%4,%5,%6,%7}, {%8,%9}, {%0,%1,%2,%3};"
        : "+f"(c[0]), "+f"(c[1]), "+f"(c[2]), "+f"(c[3])
        : "r"(a[0]), "r"(a[1]), "r"(a[2]), "r"(a[3]), "r"(b[0]), "r"(b[1]));
}

constexpr int BM = 128, BN = 128, BK = 16, THREADS = 256;
constexpr int PAD = 4;

// AT  : A global layout is [K][M] (M contiguous)  -- used for adj^T GEMM.
//       otherwise A is [M][K] (K contiguous).
// BNK : B global layout is [N][K] (K contiguous)  -- used for W.
//       otherwise B is [K][N] (N contiguous)      -- used for support.
// EPI : 0 = +bias[col] (support build), 1 = *degree[row] (output GEMMs)
template <bool AT, bool BNK, int EPI>
__global__ __launch_bounds__(THREADS, 2) void gemm_tf32(
    const float* __restrict__ A, const float* __restrict__ B,
    const float* __restrict__ aux, float* __restrict__ C, int K, int lda,
    int ldb, int ldc) {
    constexpr int A_ROWS = AT ? BK : BM;
    constexpr int A_COLS = AT ? BM : BK;
    constexpr int B_ROWS = BNK ? BN : BK;
    constexpr int B_COLS = BNK ? BK : BN;
    constexpr int A_STRIDE = A_COLS + PAD;  // 20 or 132 -> conflict-free frags
    constexpr int B_STRIDE = B_COLS + PAD;

    __shared__ uint32_t sA[2][A_ROWS * A_STRIDE];
    __shared__ uint32_t sB[2][B_ROWS * B_STRIDE];

    const int tid = threadIdx.x;
    const int lane = tid & 31;
    const int wid = tid >> 5;
    const int wm = (wid >> 2) * 64;  // warp m-offset (2 warps along M)
    const int wn = (wid & 3) * 32;   // warp n-offset (4 warps along N)
    const int g = lane >> 2;         // groupID   (0..7)
    const int t = lane & 3;          // threadID  (0..3)

    const int n0 = blockIdx.x * BN;  // n fastest -> L2 reuse of A rows
    const int m0 = blockIdx.y * BM;

    const float* gA = AT ? (A + m0) : (A + (size_t)m0 * lda);
    const float* gB = BNK ? (B + (size_t)n0 * ldb) : (B + n0);
    const size_t stepA = AT ? (size_t)BK * lda : (size_t)BK;
    const size_t stepB = BNK ? (size_t)BK : (size_t)BK * ldb;

    float acc[4][4][4];
#pragma unroll
    for (int mi = 0; mi < 4; mi++)
#pragma unroll
        for (int ni = 0; ni < 4; ni++)
#pragma unroll
            for (int i = 0; i < 4; i++) acc[mi][ni][i] = 0.f;

    float4 ra[2], rb[2];

    auto loadA = [&](const float* p) {
#pragma unroll
        for (int i = 0; i < 2; i++) {
            int e = tid + i * THREADS;  // float4 index within the tile
            int row = e / (A_COLS / 4);
            int col = (e % (A_COLS / 4)) * 4;
            ra[i] = *reinterpret_cast<const float4*>(p + (size_t)row * lda + col);
        }
    };
    auto loadB = [&](const float* p) {
#pragma unroll
        for (int i = 0; i < 2; i++) {
            int e = tid + i * THREADS;
            int row = e / (B_COLS / 4);
            int col = (e % (B_COLS / 4)) * 4;
            rb[i] = *reinterpret_cast<const float4*>(p + (size_t)row * ldb + col);
        }
    };
    auto stsA = [&](int buf) {
#pragma unroll
        for (int i = 0; i < 2; i++) {
            int e = tid + i * THREADS;
            int row = e / (A_COLS / 4);
            int col = (e % (A_COLS / 4)) * 4;
            uint4 v = {f2tf32(ra[i].x), f2tf32(ra[i].y), f2tf32(ra[i].z),
                       f2tf32(ra[i].w)};
            *reinterpret_cast<uint4*>(&sA[buf][row * A_STRIDE + col]) = v;
        }
    };
    auto stsB = [&](int buf) {
#pragma unroll
        for (int i = 0; i < 2; i++) {
            int e = tid + i * THREADS;
            int row = e / (B_COLS / 4);
            int col = (e % (B_COLS / 4)) * 4;
            uint4 v = {f2tf32(rb[i].x), f2tf32(rb[i].y), f2tf32(rb[i].z),
                       f2tf32(rb[i].w)};
            *reinterpret_cast<uint4*>(&sB[buf][row * B_STRIDE + col]) = v;
        }
    };

    auto ldAf = [&](int buf, int m, int k) -> uint32_t {
        return AT ? sA[buf][k * A_STRIDE + m] : sA[buf][m * A_STRIDE + k];
    };
    auto ldBf = [&](int buf, int k, int n) -> uint32_t {
        return BNK ? sB[buf][n * B_STRIDE + k] : sB[buf][k * B_STRIDE + n];
    };

    auto compute = [&](int buf) {
#pragma unroll
        for (int ks = 0; ks < 2; ks++) {
            const int k0 = ks * 8;
            uint32_t af[4][4];
            uint32_t bf[4][2];
#pragma unroll
            for (int mi = 0; mi < 4; mi++) {
                int m = wm + mi * 16;
                af[mi][0] = ldAf(buf, m + g, k0 + t);
                af[mi][1] = ldAf(buf, m + 8 + g, k0 + t);
                af[mi][2] = ldAf(buf, m + g, k0 + t + 4);
                af[mi][3] = ldAf(buf, m + 8 + g, k0 + t + 4);
            }
#pragma unroll
            for (int ni = 0; ni < 4; ni++) {
                int n = wn + ni * 8;
                bf[ni][0] = ldBf(buf, k0 + t, n + g);
                bf[ni][1] = ldBf(buf, k0 + t + 4, n + g);
            }
#pragma unroll
            for (int mi = 0; mi < 4; mi++)
#pragma unroll
                for (int ni = 0; ni < 4; ni++)
                    mma_tf32(acc[mi][ni], af[mi], bf[ni]);
        }
    };

    // Prologue: stage tile 0
    loadA(gA);
    loadB(gB);
    stsA(0);
    stsB(0);
    __syncthreads();

    const int kiters = K / BK;
    for (int kt = 0; kt < kiters; kt++) {
        const int cur = kt & 1;
        const int nxt = cur ^ 1;
        if (kt + 1 < kiters) {
            loadA(gA + (size_t)(kt + 1) * stepA);
            loadB(gB + (size_t)(kt + 1) * stepB);
        }
        compute(cur);
        if (kt + 1 < kiters) {
            stsA(nxt);
            stsB(nxt);
        }
        __syncthreads();
    }

    // Epilogue
    const size_t cb = (size_t)m0 * ldc + n0;
#pragma unroll
    for (int mi = 0; mi < 4; mi++) {
#pragma unroll
        for (int ni = 0; ni < 4; ni++) {
            const int r0 = wm + mi * 16 + g;
            const int c0 = wn + ni * 8 + 2 * t;
            float* p0 = C + cb + (size_t)r0 * ldc + c0;
            float* p1 = C + cb + (size_t)(r0 + 8) * ldc + c0;
            if (EPI == 0) {
                float b0v = aux[n0 + c0];
                float b1v = aux[n0 + c0 + 1];
                p0[0] = acc[mi][ni][0] + b0v;
                p0[1] = acc[mi][ni][1] + b1v;
                p1[0] = acc[mi][ni][2] + b0v;
                p1[1] = acc[mi][ni][3] + b1v;
            } else {
                float d0 = aux[m0 + r0];
                float d1 = aux[m0 + r0 + 8];
                p0[0] = d0 * acc[mi][ni][0];
                p0[1] = d0 * acc[mi][ni][1];
                p1[0] = d1 * acc[mi][ni][2];
                p1[1] = d1 * acc[mi][ni][3];
            }
        }
    }
}

extern "C" void kernel_launch(void* const* d_in, const int* in_sizes, int n_in,
                              void* d_out, int out_size) {
    const float* input = (const float*)d_in[0];   // (16384, 2048)
    const float* adj = (const float*)d_in[1];     // (8192, 8192)
    const float* degree = (const float*)d_in[2];  // (16384,)
    const float* W = (const float*)d_in[3];       // (2048, 2048)
    const float* b = (const float*)d_in[4];       // (2048,)
    float* out = (float*)d_out;                   // (16384, 2048)

    float* support = nullptr;
    cudaGetSymbolAddress((void**)&support, g_support);

    dim3 blk(THREADS);

    // GEMM1: support = input @ W^T + b   (M=16384, N=2048, K=2048)
    gemm_tf32<false, true, 0><<<dim3(DH / BN, NTOT / BM), blk>>>(
        input, W, b, support, DIN, DIN, DIN, DH);

    // GEMM2: out_u = deg_u * (adj @ sup_i)   (M=8192, N=2048, K=8192)
    gemm_tf32<false, false, 1><<<dim3(DH / BN, NU / BM), blk>>>(
        adj, support + (size_t)NU * DH, degree, out, NIT, NIT, DH, DH);

    // GEMM3: out_i = deg_i * (adj^T @ sup_u) (M=8192, N=2048, K=8192)
    gemm_tf32<true, false, 1><<<dim3(DH / BN, NIT / BM), blk>>>(
        adj, support, degree + NU, out + (size_t)NU * DH, NU, NIT, DH, DH);
}

// round 4
// speedup vs baseline: 2.5598x; 2.5598x over previous
#include <cuda_runtime.h>
#include <cuda_fp16.h>
#include <cstdint>
#include <cstddef>

#define NU   8192
#define NI   8192
#define DIN  2048
#define DH   2048
#define NTOT (NU + NI)

// ---- scratch (__device__ globals: alloc-free rule) ----
__device__ __half g_in16[(size_t)NTOT * DIN];   // 64 MB
__device__ __half g_W16[(size_t)DH * DIN];      //  8 MB
__device__ __half g_adj16[(size_t)NU * NI];     // 128 MB
__device__ __half g_adjT16[(size_t)NI * NU];    // 128 MB
__device__ __half g_supT[(size_t)DH * NTOT];    // 64 MB  support^T

// ---------------- helpers ----------------
static __device__ __forceinline__ uint32_t smem_u32(const void* p) {
    uint32_t a;
    asm("{ .reg .u64 t; cvta.to.shared.u64 t, %1; cvt.u32.u64 %0, t; }"
        : "=r"(a) : "l"(p));
    return a;
}

#define SWZ64(o) ((o) ^ (((o) >> 3) & 0x30))

#define CP_ASYNC16(dst, src) \
    asm volatile("cp.async.cg.shared.global [%0], [%1], 16;" :: "r"(dst), "l"(src) : "memory")
#define CP_COMMIT() asm volatile("cp.async.commit_group;" ::: "memory")
#define CP_WAIT2()  asm volatile("cp.async.wait_group 2;" ::: "memory")

#define LDSM_X4(r0, r1, r2, r3, addr)                                        \
    asm volatile("ldmatrix.sync.aligned.m8n8.x4.shared.b16 {%0,%1,%2,%3}, [%4];" \
        : "=r"(r0), "=r"(r1), "=r"(r2), "=r"(r3) : "r"(addr))

static __device__ __forceinline__ void mma16(float c[4], const uint32_t a[4],
                                             const uint32_t b[2]) {
    asm volatile(
        "mma.sync.aligned.m16n8k16.row.col.f32.f16.f16.f32 "
        "{%0,%1,%2,%3}, {%4,%5,%6,%7}, {%8,%9}, {%0,%1,%2,%3};"
        : "+f"(c[0]), "+f"(c[1]), "+f"(c[2]), "+f"(c[3])
        : "r"(a[0]), "r"(a[1]), "r"(a[2]), "r"(a[3]), "r"(b[0]), "r"(b[1]));
}

// ---------------- pre-pass kernels ----------------
__global__ void cvt16(const float4* __restrict__ in, uint2* __restrict__ out,
                      size_t n4) {
    size_t i = (size_t)blockIdx.x * blockDim.x + threadIdx.x;
    size_t stride = (size_t)gridDim.x * blockDim.x;
    for (; i < n4; i += stride) {
        float4 v = in[i];
        __half2 h0 = __floats2half2_rn(v.x, v.y);
        __half2 h1 = __floats2half2_rn(v.z, v.w);
        uint2 r;
        r.x = reinterpret_cast<uint32_t&>(h0);
        r.y = reinterpret_cast<uint32_t&>(h1);
        out[i] = r;
    }
}

__global__ void trans16(const float* __restrict__ A, __half* __restrict__ AT) {
    __shared__ float t[32][33];
    int bx = blockIdx.x * 32, by = blockIdx.y * 32;
    int x = threadIdx.x, y0 = threadIdx.y;
#pragma unroll
    for (int j = 0; j < 32; j += 8)
        t[y0 + j][x] = A[(size_t)(by + y0 + j) * NI + bx + x];
    __syncthreads();
#pragma unroll
    for (int j = 0; j < 32; j += 8)
        AT[(size_t)(bx + y0 + j) * NU + by + x] = __float2half(t[x][y0 + j]);
}

// ---------------- fp16 mma.sync GEMM ----------------
// D[m][n] = sum_k A[m][k]*B[n][k]; A [M][K], B [N][K], both K-major fp16.
// EPI=0: C^T fp16 store (+bias[col])  (C = supT, ldc = NTOT)
// EPI=1: C row-major fp32 (* aux[row] = degree)
constexpr int BM = 128, BN = 128, BK = 32, STAGES = 4, GT = 128;
constexpr int STAGE_A = BM * BK * 2;            // 8 KB
constexpr int STAGE_B = BN * BK * 2;            // 8 KB
constexpr int STAGE_BYTES = STAGE_A + STAGE_B;  // 16 KB
constexpr int SMEM_T = STAGES * STAGE_BYTES;    // 64 KB

template <int EPI>
__global__ __launch_bounds__(GT, 2) void gemm16(
    const __half* __restrict__ A, const __half* __restrict__ B,
    const float* __restrict__ aux, void* __restrict__ Cv, int K, int lda,
    int ldb, int ldc) {
    extern __shared__ __align__(1024) char smem[];
    const uint32_t sbase = smem_u32(smem);
    const int tid = threadIdx.x, wid = tid >> 5, lane = tid & 31;
    const int wm = (wid >> 1) * 64, wn = (wid & 1) * 64;
    const int lrow = lane & 15, lcol = lane >> 4;
    const int g = lane >> 2, t4 = lane & 3;
    const int m0 = blockIdx.y * BM, n0 = blockIdx.x * BN;

    const __half* Ab = A + (size_t)m0 * lda;
    const __half* Bb = B + (size_t)n0 * ldb;

    float acc[4][8][4];
#pragma unroll
    for (int mi = 0; mi < 4; mi++)
#pragma unroll
        for (int ni = 0; ni < 8; ni++)
#pragma unroll
            for (int i = 0; i < 4; i++) acc[mi][ni][i] = 0.f;

    // thread -> (row, 16B-chunk) for cp.async stores (4 chunks per 64B row)
    auto load_tile = [&](int kt, int st) {
        const uint32_t ab = sbase + st * STAGE_BYTES;
        const uint32_t bb = ab + STAGE_A;
        const __half* As = Ab + kt * BK;
        const __half* Bs = Bb + kt * BK;
#pragma unroll
        for (int i = 0; i < 4; i++) {
            int idx = tid + i * GT;
            int r = idx >> 2, c = idx & 3;
            CP_ASYNC16(ab + SWZ64(r * 64 + c * 16),
                       As + (size_t)r * lda + c * 8);
        }
#pragma unroll
        for (int i = 0; i < 4; i++) {
            int idx = tid + i * GT;
            int r = idx >> 2, c = idx & 3;
            CP_ASYNC16(bb + SWZ64(r * 64 + c * 16),
                       Bs + (size_t)r * ldb + c * 8);
        }
    };

    auto compute = [&](int st) {
        const uint32_t ab = sbase + st * STAGE_BYTES;
        const uint32_t bb = ab + STAGE_A;
#pragma unroll
        for (int kb = 0; kb < 2; kb++) {
            uint32_t af[4][4];
            uint32_t bf[8][2];
#pragma unroll
            for (int mi = 0; mi < 4; mi++) {
                uint32_t addr = ab + SWZ64((wm + mi * 16 + lrow) * 64 +
                                           (2 * kb + lcol) * 16);
                LDSM_X4(af[mi][0], af[mi][1], af[mi][2], af[mi][3], addr);
            }
#pragma unroll
            for (int p = 0; p < 4; p++) {
                uint32_t r0, r1, r2, r3;
                uint32_t addr = bb + SWZ64((wn + p * 16 + lrow) * 64 +
                                           (2 * kb + lcol) * 16);
                LDSM_X4(r0, r1, r2, r3, addr);
                bf[2 * p][0] = r0;
                bf[2 * p + 1][0] = r1;
                bf[2 * p][1] = r2;
                bf[2 * p + 1][1] = r3;
            }
#pragma unroll
            for (int mi = 0; mi < 4; mi++)
#pragma unroll
                for (int ni = 0; ni < 8; ni++) mma16(acc[mi][ni], af[mi], bf[ni]);
        }
    };

    const int kiters = K / BK;
#pragma unroll
    for (int t = 0; t < STAGES - 1; t++) {
        load_tile(t, t);
        CP_COMMIT();
    }

    for (int kt = 0; kt < kiters; kt++) {
        CP_WAIT2();       // tile kt resident
        __syncthreads();  // all warps done with stage being overwritten
        const int nxt = kt + STAGES - 1;
        if (nxt < kiters) load_tile(nxt, nxt & (STAGES - 1));
        CP_COMMIT();
        compute(kt & (STAGES - 1));
    }

    // ---- epilogue ----
    if (EPI == 1) {
        float* C = (float*)Cv;
#pragma unroll
        for (int mi = 0; mi < 4; mi++) {
            const int r0 = wm + mi * 16 + g;
            const float d0 = aux[m0 + r0];
            const float d1 = aux[m0 + r0 + 8];
            float* p0 = C + (size_t)(m0 + r0) * ldc + n0;
            float* p1 = C + (size_t)(m0 + r0 + 8) * ldc + n0;
#pragma unroll
            for (int ni = 0; ni < 8; ni++) {
                const int c0 = wn + ni * 8 + 2 * t4;
                float2 v0 = {d0 * acc[mi][ni][0], d0 * acc[mi][ni][1]};
                float2 v1 = {d1 * acc[mi][ni][2], d1 * acc[mi][ni][3]};
                *reinterpret_cast<float2*>(p0 + c0) = v0;
                *reinterpret_cast<float2*>(p1 + c0) = v1;
            }
        }
    } else {
        __half* C = (__half*)Cv;
#pragma unroll
        for (int mi = 0; mi < 4; mi++) {
            const int r0 = m0 + wm + mi * 16 + g;
#pragma unroll
            for (int ni = 0; ni < 8; ni++) {
                const int c0 = n0 + wn + ni * 8 + 2 * t4;
                const float b0 = aux[c0], b1 = aux[c0 + 1];
                __half* q0 = C + (size_t)c0 * ldc;
                __half* q1 = C + (size_t)(c0 + 1) * ldc;
                q0[r0] = __float2half(acc[mi][ni][0] + b0);
                q1[r0] = __float2half(acc[mi][ni][1] + b1);
                q0[r0 + 8] = __float2half(acc[mi][ni][2] + b0);
                q1[r0 + 8] = __float2half(acc[mi][ni][3] + b1);
            }
        }
    }
}

// ---------------- launch ----------------
extern "C" void kernel_launch(void* const* d_in, const int* in_sizes, int n_in,
                              void* d_out, int out_size) {
    const float* input = (const float*)d_in[0];   // (16384, 2048)
    const float* adj = (const float*)d_in[1];     // (8192, 8192)
    const float* degree = (const float*)d_in[2];  // (16384,)
    const float* W = (const float*)d_in[3];       // (2048, 2048)
    const float* b = (const float*)d_in[4];       // (2048,)
    float* out = (float*)d_out;                   // (16384, 2048)

    __half *in16, *W16, *adj16, *adjT16, *supT;
    cudaGetSymbolAddress((void**)&in16, g_in16);
    cudaGetSymbolAddress((void**)&W16, g_W16);
    cudaGetSymbolAddress((void**)&adj16, g_adj16);
    cudaGetSymbolAddress((void**)&adjT16, g_adjT16);
    cudaGetSymbolAddress((void**)&supT, g_supT);

    cudaFuncSetAttribute(gemm16<0>, cudaFuncAttributeMaxDynamicSharedMemorySize,
                         SMEM_T);
    cudaFuncSetAttribute(gemm16<1>, cudaFuncAttributeMaxDynamicSharedMemorySize,
                         SMEM_T);

    // pre-passes: fp32 -> fp16 (rne)
    cvt16<<<4096, 256>>>((const float4*)input, (uint2*)in16,
                         (size_t)NTOT * DIN / 4);
    cvt16<<<2048, 256>>>((const float4*)W, (uint2*)W16, (size_t)DH * DIN / 4);
    cvt16<<<8192, 256>>>((const float4*)adj, (uint2*)adj16,
                         (size_t)NU * NI / 4);
    trans16<<<dim3(NI / 32, NU / 32), dim3(32, 8)>>>(adj, adjT16);

    // GEMM1: supT[h][m] = fp16( sum_k in[m][k] W[h][k] + b[h] )
    gemm16<0><<<dim3(DH / BN, NTOT / BM), GT, SMEM_T>>>(
        in16, W16, b, supT, DIN, DIN, DIN, NTOT);

    // GEMM2: out_u[m][n] = deg[m] * sum_i adj[m][i] * supT[n][NU+i]
    gemm16<1><<<dim3(DH / BN, NU / BM), GT, SMEM_T>>>(
        adj16, supT + NU, degree, out, NI, NI, NTOT, DH);

    // GEMM3: out_i[m][n] = deg[NU+m] * sum_u adjT[m][u] * supT[n][u]
    gemm16<1><<<dim3(DH / BN, NI / BM), GT, SMEM_T>>>(
        adjT16, supT, degree + NU, out + (size_t)NU * DH, NU, NU, NTOT, DH);
}

// round 6
// speedup vs baseline: 2.6831x; 1.0482x over previous
#include <cuda_runtime.h>
#include <cuda_fp16.h>
#include <cstdint>
#include <cstddef>

#define NU   8192
#define NI   8192
#define DIN  2048
#define DH   2048
#define NTOT (NU + NI)

// ---- scratch (__device__ globals: alloc-free rule) ----
__device__ __half g_in16[(size_t)NTOT * DIN];   // 64 MB
__device__ __half g_W16[(size_t)DH * DIN];      //  8 MB
__device__ __half g_adj16[(size_t)NU * NI];     // 128 MB
__device__ __half g_adjT16[(size_t)NI * NU];    // 128 MB
__device__ __half g_supT[(size_t)DH * NTOT];    // 64 MB  support^T [h][m] row-major

// ---------------- helpers ----------------
static __device__ __forceinline__ uint32_t smem_u32(const void* p) {
    uint32_t a;
    asm("{ .reg .u64 t; cvta.to.shared.u64 t, %1; cvt.u32.u64 %0, t; }"
        : "=r"(a) : "l"(p));
    return a;
}

#define SWZ64(o) ((o) ^ (((o) >> 3) & 0x30))

#define CP_ASYNC16(dst, src) \
    asm volatile("cp.async.cg.shared.global [%0], [%1], 16;" :: "r"(dst), "l"(src) : "memory")
#define CP_COMMIT() asm volatile("cp.async.commit_group;" ::: "memory")
#define CP_WAIT2()  asm volatile("cp.async.wait_group 2;" ::: "memory")

#define LDSM_X4(r0, r1, r2, r3, addr)                                        \
    asm volatile("ldmatrix.sync.aligned.m8n8.x4.shared.b16 {%0,%1,%2,%3}, [%4];" \
        : "=r"(r0), "=r"(r1), "=r"(r2), "=r"(r3) : "r"(addr))

static __device__ __forceinline__ void mma16(float c[4], const uint32_t a[4],
                                             const uint32_t b[2]) {
    asm volatile(
        "mma.sync.aligned.m16n8k16.row.col.f32.f16.f16.f32 "
        "{%0,%1,%2,%3}, {%4,%5,%6,%7}, {%8,%9}, {%0,%1,%2,%3};"
        : "+f"(c[0]), "+f"(c[1]), "+f"(c[2]), "+f"(c[3])
        : "r"(a[0]), "r"(a[1]), "r"(a[2]), "r"(a[3]), "r"(b[0]), "r"(b[1]));
}

// ---------------- pre-pass kernels ----------------
__global__ void cvt16(const float4* __restrict__ in, uint2* __restrict__ out,
                      size_t n4) {
    size_t i = (size_t)blockIdx.x * blockDim.x + threadIdx.x;
    size_t stride = (size_t)gridDim.x * blockDim.x;
    for (; i < n4; i += stride) {
        float4 v = in[i];
        __half2 h0 = __floats2half2_rn(v.x, v.y);
        __half2 h1 = __floats2half2_rn(v.z, v.w);
        uint2 r;
        r.x = reinterpret_cast<uint32_t&>(h0);
        r.y = reinterpret_cast<uint32_t&>(h1);
        out[i] = r;
    }
}

// fused: adj(fp32) -> adj16 (row-major fp16) + adjT16 (transposed fp16)
// one read of adj, two fp16 writes.
__global__ void adjprep(const float* __restrict__ A, __half* __restrict__ A16,
                        __half* __restrict__ AT16) {
    __shared__ float t[32][33];
    int bx = blockIdx.x * 32, by = blockIdx.y * 32;
    int x = threadIdx.x, y0 = threadIdx.y;
#pragma unroll
    for (int j = 0; j < 32; j += 8) {
        float v = A[(size_t)(by + y0 + j) * NI + bx + x];
        t[y0 + j][x] = v;
        A16[(size_t)(by + y0 + j) * NI + bx + x] = __float2half(v);
    }
    __syncthreads();
#pragma unroll
    for (int j = 0; j < 32; j += 8)
        AT16[(size_t)(bx + y0 + j) * NU + by + x] = __float2half(t[x][y0 + j]);
}

// ---------------- fp16 mma.sync GEMM ----------------
// D[m][n] = sum_k A[m][k]*B[n][k]; A [M][K], B [N][K], both K-major fp16.
// EPI=0: C row-major fp16, + aux[row]  (supT build: A=W, B=input)
// EPI=1: C row-major fp32, * aux[row]  (degree scaling)
constexpr int BM = 128, BN = 128, BK = 32, STAGES = 4, GT = 256;
constexpr int STAGE_A = BM * BK * 2;            // 8 KB
constexpr int STAGE_B = BN * BK * 2;            // 8 KB
constexpr int STAGE_BYTES = STAGE_A + STAGE_B;  // 16 KB
constexpr int SMEM_T = STAGES * STAGE_BYTES;    // 64 KB

template <int EPI>
__global__ __launch_bounds__(GT, 2) void gemm16(
    const __half* __restrict__ A, const __half* __restrict__ B,
    const float* __restrict__ aux, void* __restrict__ Cv, int K, int lda,
    int ldb, int ldc) {
    extern __shared__ __align__(1024) char smem[];
    const uint32_t sbase = smem_u32(smem);
    const int tid = threadIdx.x, wid = tid >> 5, lane = tid & 31;
    const int wm = (wid >> 2) * 64, wn = (wid & 3) * 32;  // 8 warps: 2m x 4n
    const int lrow = lane & 15, lcol = lane >> 4;
    const int g = lane >> 2, t4 = lane & 3;
    const int m0 = blockIdx.y * BM, n0 = blockIdx.x * BN;

    const __half* Ab = A + (size_t)m0 * lda;
    const __half* Bb = B + (size_t)n0 * ldb;

    float acc[4][4][4];
#pragma unroll
    for (int mi = 0; mi < 4; mi++)
#pragma unroll
        for (int ni = 0; ni < 4; ni++)
#pragma unroll
            for (int i = 0; i < 4; i++) acc[mi][ni][i] = 0.f;

    auto load_tile = [&](int kt, int st) {
        const uint32_t ab = sbase + st * STAGE_BYTES;
        const uint32_t bb = ab + STAGE_A;
        const __half* As = Ab + kt * BK;
        const __half* Bs = Bb + kt * BK;
#pragma unroll
        for (int i = 0; i < 2; i++) {
            int idx = tid + i * GT;
            int r = idx >> 2, c = idx & 3;
            CP_ASYNC16(ab + SWZ64(r * 64 + c * 16), As + (size_t)r * lda + c * 8);
        }
#pragma unroll
        for (int i = 0; i < 2; i++) {
            int idx = tid + i * GT;
            int r = idx >> 2, c = idx & 3;
            CP_ASYNC16(bb + SWZ64(r * 64 + c * 16), Bs + (size_t)r * ldb + c * 8);
        }
    };

    auto compute = [&](int st) {
        const uint32_t ab = sbase + st * STAGE_BYTES;
        const uint32_t bb = ab + STAGE_A;
#pragma unroll
        for (int kb = 0; kb < 2; kb++) {
            uint32_t af[4][4];
            uint32_t bf[4][2];
#pragma unroll
            for (int mi = 0; mi < 4; mi++) {
                uint32_t addr = ab + SWZ64((wm + mi * 16 + lrow) * 64 +
                                           (2 * kb + lcol) * 16);
                LDSM_X4(af[mi][0], af[mi][1], af[mi][2], af[mi][3], addr);
            }
#pragma unroll
            for (int p = 0; p < 2; p++) {
                uint32_t r0, r1, r2, r3;
                uint32_t addr = bb + SWZ64((wn + p * 16 + lrow) * 64 +
                                           (2 * kb + lcol) * 16);
                LDSM_X4(r0, r1, r2, r3, addr);
                bf[2 * p][0] = r0;
                bf[2 * p + 1][0] = r1;
                bf[2 * p][1] = r2;
                bf[2 * p + 1][1] = r3;
            }
#pragma unroll
            for (int mi = 0; mi < 4; mi++)
#pragma unroll
                for (int ni = 0; ni < 4; ni++) mma16(acc[mi][ni], af[mi], bf[ni]);
        }
    };

    const int kiters = K / BK;
#pragma unroll
    for (int t = 0; t < STAGES - 1; t++) {
        load_tile(t, t);
        CP_COMMIT();
    }

    for (int kt = 0; kt < kiters; kt++) {
        CP_WAIT2();       // tile kt resident
        __syncthreads();  // all warps done with the stage being overwritten
        const int nxt = kt + STAGES - 1;
        if (nxt < kiters) load_tile(nxt, nxt & (STAGES - 1));
        CP_COMMIT();
        compute(kt & (STAGES - 1));
    }

    // ---- epilogue: row-major C, aux indexed by row ----
    if (EPI == 1) {
        float* C = (float*)Cv;
#pragma unroll
        for (int mi = 0; mi < 4; mi++) {
            const int r0 = wm + mi * 16 + g;
            const float d0 = aux[m0 + r0];
            const float d1 = aux[m0 + r0 + 8];
            float* p0 = C + (size_t)(m0 + r0) * ldc + n0;
            float* p1 = C + (size_t)(m0 + r0 + 8) * ldc + n0;
#pragma unroll
            for (int ni = 0; ni < 4; ni++) {
                const int c0 = wn + ni * 8 + 2 * t4;
                float2 v0 = {d0 * acc[mi][ni][0], d0 * acc[mi][ni][1]};
                float2 v1 = {d1 * acc[mi][ni][2], d1 * acc[mi][ni][3]};
                *reinterpret_cast<float2*>(p0 + c0) = v0;
                *reinterpret_cast<float2*>(p1 + c0) = v1;
            }
        }
    } else {
        __half* C = (__half*)Cv;
#pragma unroll
        for (int mi = 0; mi < 4; mi++) {
            const int r0 = wm + mi * 16 + g;
            const float b0 = aux[m0 + r0];
            const float b1 = aux[m0 + r0 + 8];
            __half* p0 = C + (size_t)(m0 + r0) * ldc + n0;
            __half* p1 = C + (size_t)(m0 + r0 + 8) * ldc + n0;
#pragma unroll
            for (int ni = 0; ni < 4; ni++) {
                const int c0 = wn + ni * 8 + 2 * t4;
                __half2 v0 = __floats2half2_rn(acc[mi][ni][0] + b0,
                                               acc[mi][ni][1] + b0);
                __half2 v1 = __floats2half2_rn(acc[mi][ni][2] + b1,
                                               acc[mi][ni][3] + b1);
                *reinterpret_cast<__half2*>(p0 + c0) = v0;
                *reinterpret_cast<__half2*>(p1 + c0) = v1;
            }
        }
    }
}

// ---------------- launch ----------------
extern "C" void kernel_launch(void* const* d_in, const int* in_sizes, int n_in,
                              void* d_out, int out_size) {
    const float* input = (const float*)d_in[0];   // (16384, 2048)
    const float* adj = (const float*)d_in[1];     // (8192, 8192)
    const float* degree = (const float*)d_in[2];  // (16384,)
    const float* W = (const float*)d_in[3];       // (2048, 2048)
    const float* b = (const float*)d_in[4];       // (2048,)
    float* out = (float*)d_out;                   // (16384, 2048)

    __half *in16, *W16, *adj16, *adjT16, *supT;
    cudaGetSymbolAddress((void**)&in16, g_in16);
    cudaGetSymbolAddress((void**)&W16, g_W16);
    cudaGetSymbolAddress((void**)&adj16, g_adj16);
    cudaGetSymbolAddress((void**)&adjT16, g_adjT16);
    cudaGetSymbolAddress((void**)&supT, g_supT);

    cudaFuncSetAttribute(gemm16<0>, cudaFuncAttributeMaxDynamicSharedMemorySize,
                         SMEM_T);
    cudaFuncSetAttribute(gemm16<1>, cudaFuncAttributeMaxDynamicSharedMemorySize,
                         SMEM_T);

    // pre-passes
    cvt16<<<4096, 256>>>((const float4*)input, (uint2*)in16,
                         (size_t)NTOT * DIN / 4);
    cvt16<<<2048, 256>>>((const float4*)W, (uint2*)W16, (size_t)DH * DIN / 4);
    adjprep<<<dim3(NI / 32, NU / 32), dim3(32, 8)>>>(adj, adj16, adjT16);

    // GEMM1 (transpose-free): supT[h][m] = fp16( sum_k W[h][k]*in[m][k] + b[h] )
    gemm16<0><<<dim3(NTOT / BN, DH / BM), GT, SMEM_T>>>(
        W16, in16, b, supT, DIN, DIN, DIN, NTOT);

    // GEMM2: out_u[m][n] = deg[m] * sum_i adj[m][i] * supT[n][NU+i]
    gemm16<1><<<dim3(DH / BN, NU / BM), GT, SMEM_T>>>(
        adj16, supT + NU, degree, out, NI, NI, NTOT, DH);

    // GEMM3: out_i[m][n] = deg[NU+m] * sum_u adjT[m][u] * supT[n][u]
    gemm16<1><<<dim3(DH / BN, NI / BM), GT, SMEM_T>>>(
        adjT16, supT, degree + NU, out + (size_t)NU * DH, NU, NU, NTOT, DH);
}